// round 1
// baseline (speedup 1.0000x reference)
#include <cuda_runtime.h>
#include <math.h>

#define S   48
#define MD  10
#define H   48
#define NF  60
#define WARPS 4

__device__ __forceinline__ float wsum(float v){
  #pragma unroll
  for(int o=16;o;o>>=1) v += __shfl_xor_sync(0xffffffffu,v,o);
  return v;
}
__device__ __forceinline__ float wmax(float v){
  #pragma unroll
  for(int o=16;o;o>>=1) v = fmaxf(v, __shfl_xor_sync(0xffffffffu,v,o));
  return v;
}
__device__ __forceinline__ float wmin(float v){
  #pragma unroll
  for(int o=16;o;o>>=1) v = fminf(v, __shfl_xor_sync(0xffffffffu,v,o));
  return v;
}

__global__ __launch_bounds__(WARPS*32)
void traj_kernel(const float* __restrict__ coords, const int* __restrict__ lengths,
                 const float* __restrict__ W, const float* __restrict__ bias,
                 const float* __restrict__ ln_w, const float* __restrict__ ln_b,
                 float* __restrict__ out, int B)
{
  __shared__ float shW[NF*H];
  __shared__ float shB[H], shLw[H], shLb[H];
  __shared__ float shC[WARPS][S*MD];
  __shared__ float shF[WARPS][NF];

  int tid = threadIdx.x;
  for (int k = tid; k < NF*H; k += WARPS*32) shW[k] = W[k];
  if (tid < H) { shB[tid]=bias[tid]; shLw[tid]=ln_w[tid]; shLb[tid]=ln_b[tid]; }
  __syncthreads();

  int w = tid >> 5, l = tid & 31;
  int b = blockIdx.x * WARPS + w;
  if (b >= B) return;

  const float* cp = coords + (size_t)b * (S*MD);
  float* c = shC[w];
  for (int k = l; k < S*MD; k += 32) c[k] = cp[k];
  __syncwarp();

  int n = lengths[b];
  int m = n - 1;
  float mf  = (float)m;
  float ncf = (float)(n - 2);
  int half = m >> 1;

  // per-lane state for second passes
  float dm[2];   int dmv[2];
  float cosv[2]; int cvld[2];
  float s_dm=0.f, s_f=0.f, s_s=0.f, mx_dm=-INFINITY;
  float su[MD];
  #pragma unroll
  for(int j=0;j<MD;j++) su[j]=0.f;
  float s_usq=0.f;
  float s_curv=0.f, mx_curv=-INFINITY, mn_curv=INFINITY;
  float s_cos=0.f,  mn_cos=INFINITY,  s_neg=0.f;

  #pragma unroll
  for (int rep=0; rep<2; rep++){
    int i = l + 32*rep;
    dm[rep]=0.f; dmv[rep]=0; cosv[rep]=0.f; cvld[rep]=0;
    if (i < S-1) {
      bool valid = (i < m);
      float d[MD]; float dsq=0.f;
      #pragma unroll
      for(int j=0;j<MD;j++){
        float v = valid ? (c[(i+1)*MD+j]-c[i*MD+j]) : 0.f;
        d[j]=v; dsq += v*v;
      }
      float dmag = dsq>0.f ? sqrtf(fmaxf(dsq,1e-30f)) : 0.f;
      dm[rep]=dmag; dmv[rep]=valid ? 1 : 0;
      if (valid){
        s_dm += dmag;
        if (i < half+1) s_f += dmag;
        if (i >= half)  s_s += dmag;
        mx_dm = fmaxf(mx_dm, dmag);
        float inv = 1.f / fmaxf(dmag, 1e-8f);
        #pragma unroll
        for(int j=0;j<MD;j++) su[j] += d[j]*inv;
        s_usq += dsq*inv*inv;
      }
      if (i < S-2) {   // cos index i in [0, S-3]
        bool v2 = ((i+1) < m);
        float d2[MD]; float dsq2=0.f;
        #pragma unroll
        for(int j=0;j<MD;j++){
          float v = v2 ? (c[(i+2)*MD+j]-c[(i+1)*MD+j]) : 0.f;
          d2[j]=v; dsq2 += v*v;
        }
        float dmag2 = dsq2>0.f ? sqrtf(fmaxf(dsq2,1e-30f)) : 0.f;
        float na1 = fmaxf(dm[rep], 1e-8f);
        float na2 = fmaxf(dmag2,   1e-8f);
        float dot=0.f;
        #pragma unroll
        for(int j=0;j<MD;j++) dot += d[j]*d2[j];
        float cs = dot/(na1*na2);
        cosv[rep]=cs;
        bool cvalid = (i < n-2);
        cvld[rep] = cvalid ? 1 : 0;
        if (cvalid){
          float cv = 1.f - cs;
          s_curv += cv;
          mx_curv = fmaxf(mx_curv, cv);
          mn_curv = fminf(mn_curv, cv);
          s_cos  += cs;
          mn_cos  = fminf(mn_cos, cs);
          if (cs < 0.f) s_neg += 1.f;
        }
      }
    }
  }

  float path_len  = wsum(s_dm);
  float first_sum = wsum(s_f);
  float second_sum= wsum(s_s);
  float max_dm    = wmax(mx_dm);
  float sum_curv  = wsum(s_curv);
  float max_curv  = wmax(mx_curv);
  float min_curv  = wmin(mn_curv);
  float sum_cos   = wsum(s_cos);
  float min_cos   = wmin(mn_cos);
  float neg_cnt   = wsum(s_neg);
  #pragma unroll
  for(int j=0;j<MD;j++) su[j] = wsum(su[j]);
  float sum_usq   = wsum(s_usq);

  // coord stats (two-pass over valid rows)
  float sc=0.f;
  for (int k=l; k<S*MD; k+=32) if (k < n*MD) sc += c[k];
  float cnt = (float)(n*MD);
  float mean_coord = wsum(sc)/cnt;
  float scv=0.f;
  for (int k=l; k<S*MD; k+=32) if (k < n*MD){ float d=c[k]-mean_coord; scv+=d*d; }
  float coord_var = wsum(scv)/(cnt-1.f);
  float std_coord = sqrtf(fmaxf(coord_var,1e-30f));

  // step-length stats (two-pass)
  float mean_dm = path_len/mf;
  float sdv=0.f;
  #pragma unroll
  for(int rep=0;rep<2;rep++) if(dmv[rep]){ float d=dm[rep]-mean_dm; sdv+=d*d; }
  float dm_var = wsum(sdv)/fmaxf(mf-1.f,1.f);
  float std_dm = (mf>1.f) ? sqrtf(fmaxf(dm_var,1e-30f)) : 0.f;

  // curvature variance (two-pass)
  float mean_curv = sum_curv/ncf;
  float scu=0.f;
  #pragma unroll
  for(int rep=0;rep<2;rep++) if(cvld[rep]){ float d=(1.f-cosv[rep])-mean_curv; scu+=d*d; }
  float curv_var = wsum(scu)/fmaxf(ncf-1.f,1.f);
  float std_curv = (ncf>1.f) ? sqrtf(fmaxf(curv_var,1e-30f)) : 0.f;

  // total displacement
  float td = 0.f;
  if (l < MD){ float d = c[(n-1)*MD+l]-c[l]; td = d*d; }
  float tsq = wsum(td);
  float total_disp = tsq>0.f ? sqrtf(fmaxf(tsq,1e-30f)) : 0.f;

  // parallelism via closed form: sum_{i<j} u_i.u_j = (|Su|^2 - S|u|^2)/2
  float ssq=0.f;
  #pragma unroll
  for(int j=0;j<MD;j++) ssq += su[j]*su[j];
  float npairs = mf*(mf-1.f)*0.5f;
  float parallelism = 0.5f*(ssq - sum_usq)/fmaxf(npairs,1.f);

  float disp_ratio  = total_disp/(path_len+1e-9f);
  float loop_score  = 1.f - total_disp/(path_len+1e-9f);
  float fh  = first_sum /(float)(half+1);
  float sh2 = second_sum/(float)(m-half);
  float convergence = (fh-sh2)/(fh+1e-9f);
  float cascade     = (sh2-fh)/(fh+1e-9f);
  float mean_cos    = sum_cos/ncf;
  float dir_changes = neg_cnt/fmaxf(ncf,1.f);
  float jump        = (mean_dm>1e-9f) ? max_dm/mean_dm : 1.f;

  float* f = shF[w];
  if (l==0){
    f[0]=total_disp; f[1]=path_len;   f[2]=disp_ratio; f[3]=(float)n*0.1f;
    f[4]=mean_curv;  f[5]=max_curv;   f[6]=std_curv;   f[7]=max_curv-min_curv;
    f[8]=mean_cos;   f[9]=min_cos;    f[10]=dir_changes; f[11]=disp_ratio;
    f[12]=loop_score; f[13]=convergence; f[14]=parallelism; f[15]=jump;
    f[16]=cascade;   f[17]=mean_dm;   f[18]=std_dm;    f[19]=mean_coord;
    f[20]=std_coord;
  }
  if (l < 30){
    int di = l/MD, cc = l - di*MD;
    float v = (di < m) ? (c[(di+1)*MD+cc]-c[di*MD+cc]) : 0.f;
    f[21+l] = v;
  }
  if (l < 9){
    f[51+l] = cvld[0] ? (1.f-cosv[0]) : 0.f;   // lane l holds cos index l
  }
  __syncwarp();

  // h = f @ W + b ; lane l -> outputs l and l+32 (l<16)
  float h0 = shB[l];
  float h1 = (l<16) ? shB[l+32] : 0.f;
  #pragma unroll
  for (int k=0;k<NF;k++){
    float fv = f[k];
    h0 = fmaf(fv, shW[k*H+l], h0);
    if (l<16) h1 = fmaf(fv, shW[k*H+l+32], h1);
  }
  float ssum = h0 + ((l<16) ? h1 : 0.f);
  float mu = wsum(ssum)*(1.f/48.f);
  float d0 = h0 - mu, d1 = h1 - mu;
  float vsum = d0*d0 + ((l<16) ? d1*d1 : 0.f);
  float var = wsum(vsum)*(1.f/48.f);
  float inv = 1.f/sqrtf(var+1e-5f);

  float g0 = d0*inv*shLw[l]+shLb[l];
  out[(size_t)b*H + l] = 0.5f*g0*(1.f+erff(g0*0.70710678118654752f));
  if (l<16){
    float g1 = d1*inv*shLw[l+32]+shLb[l+32];
    out[(size_t)b*H + l+32] = 0.5f*g1*(1.f+erff(g1*0.70710678118654752f));
  }
}

extern "C" void kernel_launch(void* const* d_in, const int* in_sizes, int n_in,
                              void* d_out, int out_size) {
  const float* coords = (const float*)d_in[0];
  const int*   lengths= (const int*)  d_in[1];
  const float* W      = (const float*)d_in[2];
  const float* bias   = (const float*)d_in[3];
  const float* ln_w   = (const float*)d_in[4];
  const float* ln_b   = (const float*)d_in[5];
  float* out = (float*)d_out;
  int B = in_sizes[0] / (S*MD);
  int grid = (B + WARPS - 1) / WARPS;
  traj_kernel<<<grid, WARPS*32>>>(coords, lengths, W, bias, ln_w, ln_b, out, B);
}

// round 3
// speedup vs baseline: 1.2978x; 1.2978x over previous
#include <cuda_runtime.h>
#include <math.h>

#define S    48
#define MD   10
#define H    48
#define NF   60
#define WARPS 4
#define NACC 26
#define SCR  (NACC*33 + NACC)   // 858 rows + 26 results = 884 floats (mult of 4)
#define WST  68                 // transposed-W row stride (17 x 16B granules)

__device__ __forceinline__ float wsum(float v){
  #pragma unroll
  for(int o=16;o;o>>=1) v += __shfl_xor_sync(0xffffffffu,v,o);
  return v;
}

__global__ __launch_bounds__(WARPS*32)
void traj_kernel(const float* __restrict__ coords, const int* __restrict__ lengths,
                 const float* __restrict__ W, const float* __restrict__ bias,
                 const float* __restrict__ ln_w, const float* __restrict__ ln_b,
                 float* __restrict__ out, int B)
{
  __shared__ float shWt[H*WST];                       // W transposed: [h][k], stride 68
  __shared__ float shB[H], shLw[H], shLb[H];
  __shared__ __align__(16) float shBuf[WARPS][SCR];   // coords (480) then reduce scratch
  __shared__ __align__(16) float shF[WARPS][NF];

  int tid = threadIdx.x;
  for (int idx = tid; idx < NF*H; idx += WARPS*32){
    int k = idx / H, h = idx - k*H;
    shWt[h*WST + k] = W[idx];
  }
  if (tid < H){ shB[tid]=bias[tid]; shLw[tid]=ln_w[tid]; shLb[tid]=ln_b[tid]; }
  __syncthreads();

  int w = tid >> 5, l = tid & 31;
  int b = blockIdx.x * WARPS + w;
  if (b >= B) return;

  float* cbase  = shBuf[w];
  float4* cbuf4 = (float4*)cbase;
  float*  f     = shF[w];

  int n = lengths[b];
  int m = n - 1;
  int half = m >> 1;
  int lim = n * MD;

  // ---- stage coords (float4) + fold coord sum / sumsq from registers ----
  const float4* cp4 = (const float4*)(coords + (size_t)b * (S*MD));
  float sc = 0.f, scq = 0.f;
  #pragma unroll
  for (int r = 0; r < 4; r++){
    int idx = l + 32*r;
    if (idx < S*MD/4){
      float4 v = cp4[idx];
      cbuf4[idx] = v;
      int e = idx*4;
      if (e+0 < lim){ sc += v.x; scq = fmaf(v.x,v.x,scq); }
      if (e+1 < lim){ sc += v.y; scq = fmaf(v.y,v.y,scq); }
      if (e+2 < lim){ sc += v.z; scq = fmaf(v.z,v.z,scq); }
      if (e+3 < lim){ sc += v.w; scq = fmaf(v.w,v.w,scq); }
    }
  }
  __syncwarp();

  // ---- per-lane accumulators ----
  float s_dm=0.f, s_dmsq=0.f, s_f=0.f, s_s=0.f;
  float s_curv=0.f, s_curvsq=0.f, s_cos=0.f, s_neg=0.f, s_usq=0.f;
  float su[MD];
  #pragma unroll
  for (int j=0;j<MD;j++) su[j]=0.f;
  float mx_dm=-INFINITY, mx_curv=-INFINITY, nmn_curv=-INFINITY, nmn_cos=-INFINITY;

  const float2* c2 = (const float2*)cbase;

  #pragma unroll
  for (int rep=0; rep<2; rep++){
    int i = l + 32*rep;
    if (i < S-1){
      bool valid  = (i < m);
      bool v2     = (i+1 < m);
      bool haveR2 = (i < S-2);
      float d[MD];
      float dsq=0.f, dsq2=0.f, dot=0.f;
      #pragma unroll
      for (int j=0;j<5;j++){
        float2 p0 = c2[i*5+j];
        float2 p1 = c2[(i+1)*5+j];
        float2 p2 = haveR2 ? c2[(i+2)*5+j] : make_float2(0.f,0.f);
        float dx = valid ? (p1.x-p0.x) : 0.f;
        float dy = valid ? (p1.y-p0.y) : 0.f;
        float ex = v2    ? (p2.x-p1.x) : 0.f;
        float ey = v2    ? (p2.y-p1.y) : 0.f;
        d[2*j]=dx; d[2*j+1]=dy;
        dsq  = fmaf(dx,dx,fmaf(dy,dy,dsq));
        dsq2 = fmaf(ex,ex,fmaf(ey,ey,dsq2));
        dot  = fmaf(dx,ex,fmaf(dy,ey,dot));
      }
      float dmag  = (dsq >0.f) ? sqrtf(fmaxf(dsq ,1e-30f)) : 0.f;
      float dmag2 = (dsq2>0.f) ? sqrtf(fmaxf(dsq2,1e-30f)) : 0.f;

      if (valid){
        s_dm   += dmag;
        s_dmsq += dsq;
        if (i < half+1) s_f += dmag;
        if (i >= half)  s_s += dmag;
        mx_dm = fmaxf(mx_dm, dmag);
        float inv = 1.f / fmaxf(dmag, 1e-8f);
        #pragma unroll
        for (int j=0;j<MD;j++) su[j] = fmaf(d[j], inv, su[j]);
        s_usq = fmaf(dsq, inv*inv, s_usq);
      }

      float na1 = fmaxf(dmag , 1e-8f);
      float na2 = fmaxf(dmag2, 1e-8f);
      float cs  = dot / (na1*na2);
      float cv  = 1.f - cs;
      if (v2){
        s_curv   += cv;
        s_curvsq  = fmaf(cv,cv,s_curvsq);
        mx_curv   = fmaxf(mx_curv, cv);
        nmn_curv  = fmaxf(nmn_curv, -cv);
        s_cos    += cs;
        nmn_cos   = fmaxf(nmn_cos, -cs);
        if (cs < 0.f) s_neg += 1.f;
      }

      if (rep==0){
        if (i < 3){
          #pragma unroll
          for (int j=0;j<MD;j++) f[21 + i*MD + j] = d[j];
        }
        if (i < 9) f[51 + i] = v2 ? cv : 0.f;
      }
    }
  }

  // ---- total displacement partial (reads coords; before scratch overwrite) ----
  float td = 0.f;
  if (l < MD){ float dd = cbase[(n-1)*MD + l] - cbase[l]; td = dd*dd; }
  __syncwarp();   // all coord reads done; scratch may now overwrite

  // ---- transpose-reduce: each lane writes 26 accumulators, lane j reduces acc j ----
  float* scr = cbase;
  scr[ 0*33+l]=s_dm;   scr[ 1*33+l]=s_dmsq; scr[ 2*33+l]=s_f;    scr[ 3*33+l]=s_s;
  scr[ 4*33+l]=s_curv; scr[ 5*33+l]=s_curvsq; scr[ 6*33+l]=s_cos; scr[ 7*33+l]=s_neg;
  scr[ 8*33+l]=s_usq;
  #pragma unroll
  for (int j=0;j<MD;j++) scr[(9+j)*33+l]=su[j];
  scr[19*33+l]=sc;     scr[20*33+l]=scq;    scr[21*33+l]=td;
  scr[22*33+l]=mx_dm;  scr[23*33+l]=mx_curv; scr[24*33+l]=nmn_curv; scr[25*33+l]=nmn_cos;
  __syncwarp();

  if (l < NACC){
    const float* row = scr + l*33;
    float a0=row[0], a1=row[1], a2=row[2], a3=row[3];
    float b0=a0, b1=a1;
    #pragma unroll
    for (int i=4;i<32;i+=4){
      float v0=row[i], v1=row[i+1], v2r=row[i+2], v3=row[i+3];
      a0+=v0; a1+=v1; a2+=v2r; a3+=v3;
      b0=fmaxf(b0,fmaxf(v0,v1)); b1=fmaxf(b1,fmaxf(v2r,v3));
    }
    b0=fmaxf(b0,fmaxf(row[2],row[3]));
    float ssum = (a0+a1)+(a2+a3);
    float smax = fmaxf(b0,b1);
    scr[NACC*33 + l] = (l < 22) ? ssum : smax;
  }
  __syncwarp();

  // ---- scalar features (computed redundantly on all lanes) ----
  const float* res = scr + NACC*33;
  float path_len  = res[0],  sum_dmsq  = res[1],  first_sum = res[2],  second_sum = res[3];
  float sum_curv  = res[4],  sum_curvsq= res[5],  sum_cos   = res[6],  neg_cnt    = res[7];
  float sum_usq   = res[8];
  float sum_c     = res[19], sum_cq    = res[20], tsq       = res[21];
  float max_dm    = res[22], max_curv  = res[23];
  float min_curv  = -res[24], min_cos  = -res[25];

  float mf  = (float)m;
  float ncf = (float)(n - 2);
  float cnt = (float)(n*MD);

  float mean_coord = sum_c / cnt;
  float coord_var  = (sum_cq - cnt*mean_coord*mean_coord) / (cnt-1.f);
  float std_coord  = sqrtf(fmaxf(coord_var,1e-30f));

  float mean_dm = path_len / mf;
  float dm_var  = (sum_dmsq - mf*mean_dm*mean_dm) / fmaxf(mf-1.f,1.f);
  float std_dm  = (mf>1.f) ? sqrtf(fmaxf(dm_var,1e-30f)) : 0.f;

  float mean_curv = sum_curv / ncf;
  float curv_var  = (sum_curvsq - ncf*mean_curv*mean_curv) / fmaxf(ncf-1.f,1.f);
  float std_curv  = (ncf>1.f) ? sqrtf(fmaxf(curv_var,1e-30f)) : 0.f;

  float total_disp = (tsq>0.f) ? sqrtf(fmaxf(tsq,1e-30f)) : 0.f;

  float ssq=0.f;
  #pragma unroll
  for (int j=0;j<MD;j++){ float u=res[9+j]; ssq = fmaf(u,u,ssq); }
  float npairs      = mf*(mf-1.f)*0.5f;
  float parallelism = 0.5f*(ssq - sum_usq)/fmaxf(npairs,1.f);

  float disp_ratio  = total_disp/(path_len+1e-9f);
  float loop_score  = 1.f - total_disp/(path_len+1e-9f);
  float fh  = first_sum /(float)(half+1);
  float sh2 = second_sum/(float)(m-half);
  float convergence = (fh-sh2)/(fh+1e-9f);
  float cascade     = (sh2-fh)/(fh+1e-9f);
  float mean_cos    = sum_cos/ncf;
  float dir_changes = neg_cnt/fmaxf(ncf,1.f);
  float jump        = (mean_dm>1e-9f) ? max_dm/mean_dm : 1.f;

  if (l==0){
    f[0]=total_disp; f[1]=path_len;    f[2]=disp_ratio;   f[3]=(float)n*0.1f;
    f[4]=mean_curv;  f[5]=max_curv;    f[6]=std_curv;     f[7]=max_curv-min_curv;
    f[8]=mean_cos;   f[9]=min_cos;     f[10]=dir_changes; f[11]=disp_ratio;
    f[12]=loop_score;f[13]=convergence;f[14]=parallelism; f[15]=jump;
    f[16]=cascade;   f[17]=mean_dm;    f[18]=std_dm;      f[19]=mean_coord;
    f[20]=std_coord;
  }
  __syncwarp();

  // ---- GEMV via transposed W (float4 lanes), then LN + exact GELU ----
  const float4* f4  = (const float4*)f;
  const float4* wt0 = (const float4*)&shWt[l*WST];
  const float4* wt1 = (const float4*)&shWt[(l+32)*WST];   // valid only for l<16
  float h0 = shB[l];
  float h1 = (l<16) ? shB[l+32] : 0.f;
  #pragma unroll
  for (int k4=0; k4<NF/4; k4++){
    float4 fv = f4[k4];
    float4 w0 = wt0[k4];
    h0 = fmaf(fv.x,w0.x,fmaf(fv.y,w0.y,fmaf(fv.z,w0.z,fmaf(fv.w,w0.w,h0))));
    if (l<16){
      float4 w1 = wt1[k4];
      h1 = fmaf(fv.x,w1.x,fmaf(fv.y,w1.y,fmaf(fv.z,w1.z,fmaf(fv.w,w1.w,h1))));
    }
  }
  float ssum2 = h0 + ((l<16) ? h1 : 0.f);
  float mu    = wsum(ssum2)*(1.f/48.f);
  float d0 = h0 - mu, d1 = h1 - mu;
  float vsum = d0*d0 + ((l<16) ? d1*d1 : 0.f);
  float var  = wsum(vsum)*(1.f/48.f);
  float inv  = rsqrtf(var+1e-5f);

  float g0 = d0*inv*shLw[l]+shLb[l];
  out[(size_t)b*H + l] = 0.5f*g0*(1.f+erff(g0*0.70710678118654752f));
  if (l<16){
    float g1 = d1*inv*shLw[l+32]+shLb[l+32];
    out[(size_t)b*H + l+32] = 0.5f*g1*(1.f+erff(g1*0.70710678118654752f));
  }
}

extern "C" void kernel_launch(void* const* d_in, const int* in_sizes, int n_in,
                              void* d_out, int out_size) {
  const float* coords = (const float*)d_in[0];
  const int*   lengths= (const int*)  d_in[1];
  const float* W      = (const float*)d_in[2];
  const float* bias   = (const float*)d_in[3];
  const float* ln_w   = (const float*)d_in[4];
  const float* ln_b   = (const float*)d_in[5];
  float* out = (float*)d_out;
  int B = in_sizes[0] / (S*MD);
  int grid = (B + WARPS - 1) / WARPS;
  traj_kernel<<<grid, WARPS*32>>>(coords, lengths, W, bias, ln_w, ln_b, out, B);
}

// round 4
// speedup vs baseline: 1.4825x; 1.1423x over previous
#include <cuda_runtime.h>
#include <math.h>

#define S    48
#define MD   10
#define H    48
#define NF   60
#define WARPS 4
#define NACC 26
#define SCR  (NACC*33 + NACC)   // 858 rows + 26 results = 884 floats (mult of 4)
#define WST  68                 // transposed-W row stride (17 x 16B granules)

__device__ __forceinline__ float wsum(float v){
  #pragma unroll
  for(int o=16;o;o>>=1) v += __shfl_xor_sync(0xffffffffu,v,o);
  return v;
}
// fast sqrt: x must be >= ~1e-30 (guarded by caller via fmaxf)
__device__ __forceinline__ float fsqrt_fast(float x){ return x * rsqrtf(x); }

__global__ __launch_bounds__(WARPS*32)
void traj_kernel(const float* __restrict__ coords, const int* __restrict__ lengths,
                 const float* __restrict__ W, const float* __restrict__ bias,
                 const float* __restrict__ ln_w, const float* __restrict__ ln_b,
                 float* __restrict__ out, int B)
{
  __shared__ float shWt[H*WST];                       // W transposed: [h][k], stride 68
  __shared__ float shB[H], shLw[H], shLb[H];
  __shared__ __align__(16) float shBuf[WARPS][SCR];   // coords (480) then reduce scratch
  __shared__ __align__(16) float shF[WARPS][NF];

  int tid = threadIdx.x;
  for (int idx = tid; idx < NF*H; idx += WARPS*32){
    int k = idx / H, h = idx - k*H;
    shWt[h*WST + k] = W[idx];
  }
  if (tid < H){ shB[tid]=bias[tid]; shLw[tid]=ln_w[tid]; shLb[tid]=ln_b[tid]; }
  __syncthreads();

  int w = tid >> 5, l = tid & 31;
  int b = blockIdx.x * WARPS + w;
  if (b >= B) return;

  float* cbase  = shBuf[w];
  float4* cbuf4 = (float4*)cbase;
  float*  f     = shF[w];

  int n = lengths[b];
  int m = n - 1;
  int half = m >> 1;
  int lim = n * MD;

  // ---- stage coords (float4) + fold coord sum / sumsq from registers ----
  const float4* cp4 = (const float4*)(coords + (size_t)b * (S*MD));
  float sc = 0.f, scq = 0.f;
  #pragma unroll
  for (int r = 0; r < 4; r++){
    int idx = l + 32*r;
    if (idx < S*MD/4){
      float4 v = cp4[idx];
      cbuf4[idx] = v;
      int e = idx*4;
      if (e+0 < lim){ sc += v.x; scq = fmaf(v.x,v.x,scq); }
      if (e+1 < lim){ sc += v.y; scq = fmaf(v.y,v.y,scq); }
      if (e+2 < lim){ sc += v.z; scq = fmaf(v.z,v.z,scq); }
      if (e+3 < lim){ sc += v.w; scq = fmaf(v.w,v.w,scq); }
    }
  }
  __syncwarp();

  // ---- per-lane accumulators ----
  float s_dm=0.f, s_dmsq=0.f, s_f=0.f, s_s=0.f;
  float s_curv=0.f, s_curvsq=0.f, s_cos=0.f, s_neg=0.f, s_usq=0.f;
  float su[MD];
  #pragma unroll
  for (int j=0;j<MD;j++) su[j]=0.f;
  float mx_dm=-INFINITY, mx_curv=-INFINITY, nmn_curv=-INFINITY, nmn_cos=-INFINITY;

  const float2* c2 = (const float2*)cbase;

  #pragma unroll
  for (int rep=0; rep<2; rep++){
    int i = l + 32*rep;
    if (i < S-1){
      bool valid  = (i < m);
      bool v2     = (i+1 < m);
      bool haveR2 = (i < S-2);
      float d[MD];
      float dsq=0.f, dsq2=0.f, dot=0.f;
      #pragma unroll
      for (int j=0;j<5;j++){
        float2 p0 = c2[i*5+j];
        float2 p1 = c2[(i+1)*5+j];
        float2 p2 = haveR2 ? c2[(i+2)*5+j] : make_float2(0.f,0.f);
        float dx = valid ? (p1.x-p0.x) : 0.f;
        float dy = valid ? (p1.y-p0.y) : 0.f;
        float ex = v2    ? (p2.x-p1.x) : 0.f;
        float ey = v2    ? (p2.y-p1.y) : 0.f;
        d[2*j]=dx; d[2*j+1]=dy;
        dsq  = fmaf(dx,dx,fmaf(dy,dy,dsq));
        dsq2 = fmaf(ex,ex,fmaf(ey,ey,dsq2));
        dot  = fmaf(dx,ex,fmaf(dy,ey,dot));
      }
      float dmag  = (dsq >0.f) ? fsqrt_fast(fmaxf(dsq ,1e-30f)) : 0.f;
      float dmag2 = (dsq2>0.f) ? fsqrt_fast(fmaxf(dsq2,1e-30f)) : 0.f;

      float inv1 = __fdividef(1.f, fmaxf(dmag , 1e-8f));
      float inv2 = __fdividef(1.f, fmaxf(dmag2, 1e-8f));

      if (valid){
        s_dm   += dmag;
        s_dmsq += dsq;
        if (i < half+1) s_f += dmag;
        if (i >= half)  s_s += dmag;
        mx_dm = fmaxf(mx_dm, dmag);
        #pragma unroll
        for (int j=0;j<MD;j++) su[j] = fmaf(d[j], inv1, su[j]);
        s_usq = fmaf(dsq, inv1*inv1, s_usq);
      }

      float cs  = dot * inv1 * inv2;
      float cv  = 1.f - cs;
      if (v2){
        s_curv   += cv;
        s_curvsq  = fmaf(cv,cv,s_curvsq);
        mx_curv   = fmaxf(mx_curv, cv);
        nmn_curv  = fmaxf(nmn_curv, -cv);
        s_cos    += cs;
        nmn_cos   = fmaxf(nmn_cos, -cs);
        if (cs < 0.f) s_neg += 1.f;
      }

      if (rep==0){
        if (i < 3){
          #pragma unroll
          for (int j=0;j<MD;j++) f[21 + i*MD + j] = d[j];
        }
        if (i < 9) f[51 + i] = v2 ? cv : 0.f;
      }
    }
  }

  // ---- total displacement partial (reads coords; before scratch overwrite) ----
  float td = 0.f;
  if (l < MD){ float dd = cbase[(n-1)*MD + l] - cbase[l]; td = dd*dd; }
  __syncwarp();   // all coord reads done; scratch may now overwrite

  // ---- transpose-reduce: each lane writes 26 accumulators, lane j reduces acc j ----
  float* scr = cbase;
  scr[ 0*33+l]=s_dm;   scr[ 1*33+l]=s_dmsq; scr[ 2*33+l]=s_f;    scr[ 3*33+l]=s_s;
  scr[ 4*33+l]=s_curv; scr[ 5*33+l]=s_curvsq; scr[ 6*33+l]=s_cos; scr[ 7*33+l]=s_neg;
  scr[ 8*33+l]=s_usq;
  #pragma unroll
  for (int j=0;j<MD;j++) scr[(9+j)*33+l]=su[j];
  scr[19*33+l]=sc;     scr[20*33+l]=scq;    scr[21*33+l]=td;
  scr[22*33+l]=mx_dm;  scr[23*33+l]=mx_curv; scr[24*33+l]=nmn_curv; scr[25*33+l]=nmn_cos;
  __syncwarp();

  if (l < NACC){
    const float* row = scr + l*33;
    float a0=row[0], a1=row[1], a2=row[2], a3=row[3];
    float b0=a0, b1=a1;
    #pragma unroll
    for (int i=4;i<32;i+=4){
      float v0=row[i], v1=row[i+1], v2r=row[i+2], v3=row[i+3];
      a0+=v0; a1+=v1; a2+=v2r; a3+=v3;
      b0=fmaxf(b0,fmaxf(v0,v1)); b1=fmaxf(b1,fmaxf(v2r,v3));
    }
    b0=fmaxf(b0,fmaxf(row[2],row[3]));
    float ssum = (a0+a1)+(a2+a3);
    float smax = fmaxf(b0,b1);
    scr[NACC*33 + l] = (l < 22) ? ssum : smax;
  }
  __syncwarp();

  // ---- scalar features (computed redundantly on all lanes) ----
  const float* res = scr + NACC*33;
  float path_len  = res[0],  sum_dmsq  = res[1],  first_sum = res[2],  second_sum = res[3];
  float sum_curv  = res[4],  sum_curvsq= res[5],  sum_cos   = res[6],  neg_cnt    = res[7];
  float sum_usq   = res[8];
  float sum_c     = res[19], sum_cq    = res[20], tsq       = res[21];
  float max_dm    = res[22], max_curv  = res[23];
  float min_curv  = -res[24], min_cos  = -res[25];

  float mf  = (float)m;
  float ncf = (float)(n - 2);
  float cnt = (float)(n*MD);
  float rncf = __fdividef(1.f, ncf);

  float mean_coord = __fdividef(sum_c, cnt);
  float coord_var  = __fdividef(sum_cq - cnt*mean_coord*mean_coord, cnt-1.f);
  float std_coord  = fsqrt_fast(fmaxf(coord_var,1e-30f));

  float mean_dm = __fdividef(path_len, mf);
  float dm_var  = __fdividef(sum_dmsq - mf*mean_dm*mean_dm, fmaxf(mf-1.f,1.f));
  float std_dm  = (mf>1.f) ? fsqrt_fast(fmaxf(dm_var,1e-30f)) : 0.f;

  float mean_curv = sum_curv * rncf;
  float curv_var  = __fdividef(sum_curvsq - ncf*mean_curv*mean_curv, fmaxf(ncf-1.f,1.f));
  float std_curv  = (ncf>1.f) ? fsqrt_fast(fmaxf(curv_var,1e-30f)) : 0.f;

  float total_disp = (tsq>0.f) ? fsqrt_fast(fmaxf(tsq,1e-30f)) : 0.f;

  float ssq=0.f;
  #pragma unroll
  for (int j=0;j<MD;j++){ float u=res[9+j]; ssq = fmaf(u,u,ssq); }
  float npairs      = mf*(mf-1.f)*0.5f;
  float parallelism = 0.5f*(ssq - sum_usq)*__fdividef(1.f, fmaxf(npairs,1.f));

  float rpl = __fdividef(1.f, path_len+1e-9f);
  float disp_ratio  = total_disp * rpl;
  float loop_score  = 1.f - total_disp * rpl;
  float fh  = __fdividef(first_sum , (float)(half+1));
  float sh2 = __fdividef(second_sum, (float)(m-half));
  float rfh = __fdividef(1.f, fh+1e-9f);
  float convergence = (fh-sh2)*rfh;
  float cascade     = (sh2-fh)*rfh;
  float mean_cos    = sum_cos * rncf;
  float dir_changes = neg_cnt * __fdividef(1.f, fmaxf(ncf,1.f));
  float jump        = (mean_dm>1e-9f) ? __fdividef(max_dm, mean_dm) : 1.f;

  if (l==0){
    f[0]=total_disp; f[1]=path_len;    f[2]=disp_ratio;   f[3]=(float)n*0.1f;
    f[4]=mean_curv;  f[5]=max_curv;    f[6]=std_curv;     f[7]=max_curv-min_curv;
    f[8]=mean_cos;   f[9]=min_cos;     f[10]=dir_changes; f[11]=disp_ratio;
    f[12]=loop_score;f[13]=convergence;f[14]=parallelism; f[15]=jump;
    f[16]=cascade;   f[17]=mean_dm;    f[18]=std_dm;      f[19]=mean_coord;
    f[20]=std_coord;
  }
  __syncwarp();

  // ---- GEMV via transposed W (float4 lanes), then LN + exact GELU ----
  const float4* f4  = (const float4*)f;
  const float4* wt0 = (const float4*)&shWt[l*WST];
  const float4* wt1 = (const float4*)&shWt[(l+32)*WST];   // valid only for l<16
  float h0 = shB[l];
  float h1 = (l<16) ? shB[l+32] : 0.f;
  #pragma unroll
  for (int k4=0; k4<NF/4; k4++){
    float4 fv = f4[k4];
    float4 w0 = wt0[k4];
    h0 = fmaf(fv.x,w0.x,fmaf(fv.y,w0.y,fmaf(fv.z,w0.z,fmaf(fv.w,w0.w,h0))));
    if (l<16){
      float4 w1 = wt1[k4];
      h1 = fmaf(fv.x,w1.x,fmaf(fv.y,w1.y,fmaf(fv.z,w1.z,fmaf(fv.w,w1.w,h1))));
    }
  }
  float ssum2 = h0 + ((l<16) ? h1 : 0.f);
  float mu    = wsum(ssum2)*(1.f/48.f);
  float d0 = h0 - mu, d1 = h1 - mu;
  float vsum = d0*d0 + ((l<16) ? d1*d1 : 0.f);
  float var  = wsum(vsum)*(1.f/48.f);
  float inv  = rsqrtf(var+1e-5f);

  float g0 = d0*inv*shLw[l]+shLb[l];
  out[(size_t)b*H + l] = 0.5f*g0*(1.f+erff(g0*0.70710678118654752f));
  if (l<16){
    float g1 = d1*inv*shLw[l+32]+shLb[l+32];
    out[(size_t)b*H + l+32] = 0.5f*g1*(1.f+erff(g1*0.70710678118654752f));
  }
}

extern "C" void kernel_launch(void* const* d_in, const int* in_sizes, int n_in,
                              void* d_out, int out_size) {
  const float* coords = (const float*)d_in[0];
  const int*   lengths= (const int*)  d_in[1];
  const float* W      = (const float*)d_in[2];
  const float* bias   = (const float*)d_in[3];
  const float* ln_w   = (const float*)d_in[4];
  const float* ln_b   = (const float*)d_in[5];
  float* out = (float*)d_out;
  int B = in_sizes[0] / (S*MD);
  int grid = (B + WARPS - 1) / WARPS;
  traj_kernel<<<grid, WARPS*32>>>(coords, lengths, W, bias, ln_w, ln_b, out, B);
}

// round 5
// speedup vs baseline: 1.8146x; 1.2240x over previous
#include <cuda_runtime.h>
#include <math.h>

#define S    48
#define MD   10
#define H    48
#define NF   60
#define WARPS 4
#define T    4                  // trajectories per warp
#define NACC 26
#define SCR  (NACC*33 + NACC)   // 858 rows + 26 results = 884 floats
#define WST  68                 // transposed-W row stride (17 x 16B granules)

__device__ __forceinline__ float wsum(float v){
  #pragma unroll
  for(int o=16;o;o>>=1) v += __shfl_xor_sync(0xffffffffu,v,o);
  return v;
}
// fast sqrt: x must be >= ~1e-30 (guarded by caller via fmaxf)
__device__ __forceinline__ float fsqrt_fast(float x){ return x * rsqrtf(x); }

__global__ __launch_bounds__(WARPS*32, 6)
void traj_kernel(const float* __restrict__ coords, const int* __restrict__ lengths,
                 const float* __restrict__ W, const float* __restrict__ bias,
                 const float* __restrict__ ln_w, const float* __restrict__ ln_b,
                 float* __restrict__ out, int B)
{
  __shared__ float shWt[H*WST];                       // W transposed: [h][k], stride 68
  __shared__ float shB[H], shLw[H], shLb[H];
  __shared__ __align__(16) float shBuf[WARPS][SCR];   // coords (480) then reduce scratch
  __shared__ __align__(16) float shF[WARPS][T*NF];    // features for T trajectories

  int tid = threadIdx.x;
  for (int idx = tid; idx < NF*H; idx += WARPS*32){
    int k = idx / H, h = idx - k*H;
    shWt[h*WST + k] = W[idx];
  }
  if (tid < H){ shB[tid]=bias[tid]; shLw[tid]=ln_w[tid]; shLb[tid]=ln_b[tid]; }
  __syncthreads();

  int w = tid >> 5, l = tid & 31;
  int b0 = (blockIdx.x * WARPS + w) * T;

  float* cbase  = shBuf[w];
  float4* cbuf4 = (float4*)cbase;
  const float2* c2 = (const float2*)cbase;

  // ================= feature phase: T trajectories sequentially =================
  for (int t = 0; t < T; t++){
    int b = b0 + t;
    if (b >= B) break;
    float* f = shF[w] + t*NF;

    int n = lengths[b];
    int m = n - 1;
    int half = m >> 1;
    int lim = n * MD;

    // ---- stage coords (float4) + fold coord sum / sumsq from registers ----
    const float4* cp4 = (const float4*)(coords + (size_t)b * (S*MD));
    float sc = 0.f, scq = 0.f;
    #pragma unroll
    for (int r = 0; r < 4; r++){
      int idx = l + 32*r;
      if (idx < S*MD/4){
        float4 v = cp4[idx];
        cbuf4[idx] = v;
        int e = idx*4;
        if (e+0 < lim){ sc += v.x; scq = fmaf(v.x,v.x,scq); }
        if (e+1 < lim){ sc += v.y; scq = fmaf(v.y,v.y,scq); }
        if (e+2 < lim){ sc += v.z; scq = fmaf(v.z,v.z,scq); }
        if (e+3 < lim){ sc += v.w; scq = fmaf(v.w,v.w,scq); }
      }
    }
    __syncwarp();

    // ---- per-lane accumulators ----
    float s_dm=0.f, s_dmsq=0.f, s_f=0.f, s_s=0.f;
    float s_curv=0.f, s_curvsq=0.f, s_cos=0.f, s_neg=0.f, s_usq=0.f;
    float su[MD];
    #pragma unroll
    for (int j=0;j<MD;j++) su[j]=0.f;
    float mx_dm=-INFINITY, mx_curv=-INFINITY, nmn_curv=-INFINITY, nmn_cos=-INFINITY;

    #pragma unroll
    for (int rep=0; rep<2; rep++){
      int i = l + 32*rep;
      if (i < S-1){
        bool valid  = (i < m);
        bool v2     = (i+1 < m);
        bool haveR2 = (i < S-2);
        float d[MD];
        float dsq=0.f, dsq2=0.f, dot=0.f;
        #pragma unroll
        for (int j=0;j<5;j++){
          float2 p0 = c2[i*5+j];
          float2 p1 = c2[(i+1)*5+j];
          float2 p2 = haveR2 ? c2[(i+2)*5+j] : make_float2(0.f,0.f);
          float dx = valid ? (p1.x-p0.x) : 0.f;
          float dy = valid ? (p1.y-p0.y) : 0.f;
          float ex = v2    ? (p2.x-p1.x) : 0.f;
          float ey = v2    ? (p2.y-p1.y) : 0.f;
          d[2*j]=dx; d[2*j+1]=dy;
          dsq  = fmaf(dx,dx,fmaf(dy,dy,dsq));
          dsq2 = fmaf(ex,ex,fmaf(ey,ey,dsq2));
          dot  = fmaf(dx,ex,fmaf(dy,ey,dot));
        }
        float dmag  = (dsq >0.f) ? fsqrt_fast(fmaxf(dsq ,1e-30f)) : 0.f;
        float dmag2 = (dsq2>0.f) ? fsqrt_fast(fmaxf(dsq2,1e-30f)) : 0.f;

        float inv1 = __fdividef(1.f, fmaxf(dmag , 1e-8f));
        float inv2 = __fdividef(1.f, fmaxf(dmag2, 1e-8f));

        if (valid){
          s_dm   += dmag;
          s_dmsq += dsq;
          if (i < half+1) s_f += dmag;
          if (i >= half)  s_s += dmag;
          mx_dm = fmaxf(mx_dm, dmag);
          #pragma unroll
          for (int j=0;j<MD;j++) su[j] = fmaf(d[j], inv1, su[j]);
          s_usq = fmaf(dsq, inv1*inv1, s_usq);
        }

        float cs  = dot * inv1 * inv2;
        float cv  = 1.f - cs;
        if (v2){
          s_curv   += cv;
          s_curvsq  = fmaf(cv,cv,s_curvsq);
          mx_curv   = fmaxf(mx_curv, cv);
          nmn_curv  = fmaxf(nmn_curv, -cv);
          s_cos    += cs;
          nmn_cos   = fmaxf(nmn_cos, -cs);
          if (cs < 0.f) s_neg += 1.f;
        }

        if (rep==0){
          if (i < 3){
            #pragma unroll
            for (int j=0;j<MD;j++) f[21 + i*MD + j] = d[j];
          }
          if (i < 9) f[51 + i] = v2 ? cv : 0.f;
        }
      }
    }

    // ---- total displacement partial (reads coords; before scratch overwrite) ----
    float td = 0.f;
    if (l < MD){ float dd = cbase[(n-1)*MD + l] - cbase[l]; td = dd*dd; }
    __syncwarp();   // all coord reads done; scratch may now overwrite

    // ---- transpose-reduce ----
    float* scr = cbase;
    scr[ 0*33+l]=s_dm;   scr[ 1*33+l]=s_dmsq;  scr[ 2*33+l]=s_f;   scr[ 3*33+l]=s_s;
    scr[ 4*33+l]=s_curv; scr[ 5*33+l]=s_curvsq; scr[ 6*33+l]=s_cos; scr[ 7*33+l]=s_neg;
    scr[ 8*33+l]=s_usq;
    #pragma unroll
    for (int j=0;j<MD;j++) scr[(9+j)*33+l]=su[j];
    scr[19*33+l]=sc;     scr[20*33+l]=scq;     scr[21*33+l]=td;
    scr[22*33+l]=mx_dm;  scr[23*33+l]=mx_curv; scr[24*33+l]=nmn_curv; scr[25*33+l]=nmn_cos;
    __syncwarp();

    if (l < NACC){
      const float* row = scr + l*33;
      float a0=row[0], a1=row[1], a2=row[2], a3=row[3];
      float b0m=a0, b1m=a1;
      #pragma unroll
      for (int i=4;i<32;i+=4){
        float v0=row[i], v1=row[i+1], v2r=row[i+2], v3=row[i+3];
        a0+=v0; a1+=v1; a2+=v2r; a3+=v3;
        b0m=fmaxf(b0m,fmaxf(v0,v1)); b1m=fmaxf(b1m,fmaxf(v2r,v3));
      }
      b0m=fmaxf(b0m,fmaxf(row[2],row[3]));
      float ssum = (a0+a1)+(a2+a3);
      float smax = fmaxf(b0m,b1m);
      scr[NACC*33 + l] = (l < 22) ? ssum : smax;
    }
    __syncwarp();

    // ---- scalar features (lane 0 only; others' loads dead) ----
    if (l == 0){
      const float* res = scr + NACC*33;
      float path_len  = res[0],  sum_dmsq  = res[1],  first_sum = res[2],  second_sum = res[3];
      float sum_curv  = res[4],  sum_curvsq= res[5],  sum_cos   = res[6],  neg_cnt    = res[7];
      float sum_usq   = res[8];
      float sum_c     = res[19], sum_cq    = res[20], tsq       = res[21];
      float max_dm    = res[22], max_curv  = res[23];
      float min_curv  = -res[24], min_cos  = -res[25];

      float mf  = (float)m;
      float ncf = (float)(n - 2);
      float cnt = (float)(n*MD);
      float rncf = __fdividef(1.f, ncf);

      float mean_coord = __fdividef(sum_c, cnt);
      float coord_var  = __fdividef(sum_cq - cnt*mean_coord*mean_coord, cnt-1.f);
      float std_coord  = fsqrt_fast(fmaxf(coord_var,1e-30f));

      float mean_dm = __fdividef(path_len, mf);
      float dm_var  = __fdividef(sum_dmsq - mf*mean_dm*mean_dm, fmaxf(mf-1.f,1.f));
      float std_dm  = (mf>1.f) ? fsqrt_fast(fmaxf(dm_var,1e-30f)) : 0.f;

      float mean_curv = sum_curv * rncf;
      float curv_var  = __fdividef(sum_curvsq - ncf*mean_curv*mean_curv, fmaxf(ncf-1.f,1.f));
      float std_curv  = (ncf>1.f) ? fsqrt_fast(fmaxf(curv_var,1e-30f)) : 0.f;

      float total_disp = (tsq>0.f) ? fsqrt_fast(fmaxf(tsq,1e-30f)) : 0.f;

      float ssq=0.f;
      #pragma unroll
      for (int j=0;j<MD;j++){ float u=res[9+j]; ssq = fmaf(u,u,ssq); }
      float npairs      = mf*(mf-1.f)*0.5f;
      float parallelism = 0.5f*(ssq - sum_usq)*__fdividef(1.f, fmaxf(npairs,1.f));

      float rpl = __fdividef(1.f, path_len+1e-9f);
      float disp_ratio  = total_disp * rpl;
      float loop_score  = 1.f - total_disp * rpl;
      float fh  = __fdividef(first_sum , (float)(half+1));
      float sh2 = __fdividef(second_sum, (float)(m-half));
      float rfh = __fdividef(1.f, fh+1e-9f);
      float convergence = (fh-sh2)*rfh;
      float cascade     = (sh2-fh)*rfh;
      float mean_cos    = sum_cos * rncf;
      float dir_changes = neg_cnt * __fdividef(1.f, fmaxf(ncf,1.f));
      float jump        = (mean_dm>1e-9f) ? __fdividef(max_dm, mean_dm) : 1.f;

      f[0]=total_disp; f[1]=path_len;    f[2]=disp_ratio;   f[3]=(float)n*0.1f;
      f[4]=mean_curv;  f[5]=max_curv;    f[6]=std_curv;     f[7]=max_curv-min_curv;
      f[8]=mean_cos;   f[9]=min_cos;     f[10]=dir_changes; f[11]=disp_ratio;
      f[12]=loop_score;f[13]=convergence;f[14]=parallelism; f[15]=jump;
      f[16]=cascade;   f[17]=mean_dm;    f[18]=std_dm;      f[19]=mean_coord;
      f[20]=std_coord;
    }
    __syncwarp();
  }

  // ================= batched GEMV: one W read serves T trajectories =============
  const float4* f4b = (const float4*)shF[w];          // [T*15] float4s
  const float4* wt0 = (const float4*)&shWt[l*WST];
  const float4* wt1 = (const float4*)&shWt[(l+32)*WST];  // used only when l<16
  float h0a[T], h1a[T];
  #pragma unroll
  for (int t=0;t<T;t++){ h0a[t]=shB[l]; h1a[t]=(l<16)?shB[l+32]:0.f; }

  #pragma unroll
  for (int k4=0; k4<NF/4; k4++){
    float4 w0 = wt0[k4];
    float4 w1 = make_float4(0.f,0.f,0.f,0.f);
    if (l<16) w1 = wt1[k4];
    #pragma unroll
    for (int t=0;t<T;t++){
      float4 fv = f4b[t*(NF/4)+k4];
      h0a[t] = fmaf(fv.x,w0.x,fmaf(fv.y,w0.y,fmaf(fv.z,w0.z,fmaf(fv.w,w0.w,h0a[t]))));
      h1a[t] = fmaf(fv.x,w1.x,fmaf(fv.y,w1.y,fmaf(fv.z,w1.z,fmaf(fv.w,w1.w,h1a[t]))));
    }
  }

  // ================= LayerNorm + exact GELU per trajectory ======================
  #pragma unroll
  for (int t=0;t<T;t++){
    int b = b0 + t;
    if (b >= B) break;
    float ssum2 = h0a[t] + ((l<16) ? h1a[t] : 0.f);
    float mu    = wsum(ssum2)*(1.f/48.f);
    float d0 = h0a[t] - mu, d1 = h1a[t] - mu;
    float vsum = d0*d0 + ((l<16) ? d1*d1 : 0.f);
    float var  = wsum(vsum)*(1.f/48.f);
    float inv  = rsqrtf(var+1e-5f);

    float g0 = d0*inv*shLw[l]+shLb[l];
    out[(size_t)b*H + l] = 0.5f*g0*(1.f+erff(g0*0.70710678118654752f));
    if (l<16){
      float g1 = d1*inv*shLw[l+32]+shLb[l+32];
      out[(size_t)b*H + l+32] = 0.5f*g1*(1.f+erff(g1*0.70710678118654752f));
    }
  }
}

extern "C" void kernel_launch(void* const* d_in, const int* in_sizes, int n_in,
                              void* d_out, int out_size) {
  const float* coords = (const float*)d_in[0];
  const int*   lengths= (const int*)  d_in[1];
  const float* W      = (const float*)d_in[2];
  const float* bias   = (const float*)d_in[3];
  const float* ln_w   = (const float*)d_in[4];
  const float* ln_b   = (const float*)d_in[5];
  float* out = (float*)d_out;
  int B = in_sizes[0] / (S*MD);
  int per_block = WARPS * T;
  int grid = (B + per_block - 1) / per_block;
  traj_kernel<<<grid, WARPS*32>>>(coords, lengths, W, bias, ln_w, ln_b, out, B);
}